// round 4
// baseline (speedup 1.0000x reference)
#include <cuda_runtime.h>
#include <cuda_bf16.h>

#define E_EVENTS 1024
#define B_SAMPLES 256
#define DIN 784
#define DH 400
#define DOUT 10
#define CHUNK 32
#define NCHUNK (E_EVENTS / CHUNK)
#define CAP_WG   640     // gathered-weight slots per chunk (avg ~224 expected)
#define CAP_LIST 2048    // index-list slots per chunk (fallback tier 1)
#define NTHREADS 480

// Scratch (no cudaMalloc allowed): transposed+prepped weights.
__device__ float g_W1T[DIN * DH];   // [784][400]
__device__ float g_W2c[DH * DOUT];  // [400][10] : W2[d][j] + b2[d]/400

__global__ void prep_kernel(const float* __restrict__ W1,
                            const float* __restrict__ W2,
                            const float* __restrict__ b2) {
    int idx = blockIdx.x * blockDim.x + threadIdx.x;
    if (idx < DIN * DH) {
        int p = idx / DH;
        int j = idx - p * DH;
        g_W1T[idx] = W1[j * DIN + p];
    } else if (idx < DIN * DH + DH * DOUT) {
        int i = idx - DIN * DH;
        int j = i / DOUT;
        int d = i - j * DOUT;
        g_W2c[i] = __fadd_rn(W2[d * DH + j], __fdiv_rn(b2[d], 400.0f));
    }
}

// Dynamic shared layout sizes (bytes)
#define SM_BYTES (E_EVENTS*4 /*dec1*/ + E_EVENTS*4 /*dec2*/ + DH*DOUT*4 /*W2c*/ \
                + E_EVENTS*4 /*pix*/ + 4*CHUNK*16*4 /*mask*/ \
                + 2*CAP_LIST*2 /*elist*/ + 2*CAP_WG*DOUT*4 /*wg*/ \
                + 2*CHUNK*4 /*off*/ + 2*CHUNK*4 /*cnt*/ + 2*4 /*tot*/ + 64)

// One CTA per sample, 15 warps:
//  warps 0..12  : layer-1 neurons (threads 0..399 active), produce fired masks
//  warp 14      : compactor — masks(k-1) -> spike list + gathered weights
//  warp 13      : layer-2 chain — consumes gathered weights of chunk k-2
__global__ __launch_bounds__(NTHREADS, 2) void snn_kernel(
    const float* __restrict__ times,
    const int*   __restrict__ pix,
    const float* __restrict__ b1,
    float*       __restrict__ out)
{
    extern __shared__ unsigned char dyn[];
    float*          s_dec1  = (float*)dyn;                          // [E]
    float*          s_dec2  = s_dec1 + E_EVENTS;                    // [E]
    float*          s_W2c   = s_dec2 + E_EVENTS;                    // [4000]
    int*            s_pix   = (int*)(s_W2c + DH * DOUT);            // [E]
    unsigned*       s_mask  = (unsigned*)(s_pix + E_EVENTS);        // [4][CHUNK][16]
    unsigned short* s_elist = (unsigned short*)(s_mask + 4*CHUNK*16); // [2][CAP_LIST]
    float*          s_wg    = (float*)(s_elist + 2*CAP_LIST);       // [2][CAP_WG*10]
    int*            s_off   = (int*)(s_wg + 2*CAP_WG*DOUT);         // [2][CHUNK]
    int*            s_cnt   = s_off + 2*CHUNK;                      // [2][CHUNK]
    int*            s_tot   = s_cnt + 2*CHUNK;                      // [2]

    const float TAUF = 0.6213349345596119f;  // float(-1/ln(0.2))
    const int b    = blockIdx.x;
    const int tid  = threadIdx.x;
    const int warp = tid >> 5;
    const int lane = tid & 31;

    for (int i = tid; i < E_EVENTS; i += NTHREADS)
        s_pix[i] = pix[b * E_EVENTS + i];
    for (int i = tid; i < DH * DOUT; i += NTHREADS) s_W2c[i] = g_W2c[i];
    for (int i = tid; i < 4 * CHUNK * 16; i += NTHREADS) s_mask[i] = 0u;
    __syncthreads();

    // Precompute decays (exact reference f32 expressions)
    for (int e = tid; e < E_EVENTS; e += NTHREADS) {
        float t  = times[b * E_EVENTS + e];
        float tp = (e > 0) ? times[b * E_EVENTS + e - 1] : 0.0f;
        s_dec1[e] = expf(__fdiv_rn(-(t - tp), TAUF));
        float th  = __fadd_rn(t, 0.1f);
        float thp = (e > 0) ? __fadd_rn(tp, 0.1f) : 0.0f;
        s_dec2[e] = expf(__fdiv_rn(-(th - thp), TAUF));
    }
    __syncthreads();

    // ---- per-role state ----
    float h1 = 0.0f, bias1j = 0.0f;
    if (tid < DH) bias1j = __fdiv_rn(b1[tid], 784.0f);
    float wv = (tid < DH) ? g_W1T[s_pix[0] * DH + tid] : 0.0f;  // event-0 weight

    float h2 = 0.0f, cnt = 0.0f;                                 // chain warp (13)

    for (int k = 0; k < NCHUNK + 2; ++k) {
        if (warp <= 12) {
            // -------- layer 1: produce masks for chunk k --------
            if (k < NCHUNK) {
                unsigned* mrow = s_mask + (k & 3) * CHUNK * 16;
                #pragma unroll 8
                for (int e0 = 0; e0 < CHUNK; ++e0) {
                    const int e = k * CHUNK + e0;
                    float wnext = 0.0f;
                    if (e + 1 < E_EVENTS && tid < DH)
                        wnext = g_W1T[s_pix[e + 1] * DH + tid];
                    float d = s_dec1[e];
                    bool fired = false;
                    if (tid < DH) {
                        h1 = __fadd_rn(__fadd_rn(__fmul_rn(h1, d), wv), bias1j);
                        fired = (h1 >= 0.5f);
                        if (fired) h1 = 0.0f;
                    }
                    unsigned m = __ballot_sync(0xffffffffu, fired);
                    if (lane == 0) mrow[e0 * 16 + warp] = m;
                    wv = wnext;
                }
            }
        } else if (warp == 14) {
            // -------- compactor: chunk k-1 masks -> list + gathered weights --------
            const int kc = k - 1;
            if (kc >= 0 && kc < NCHUNK) {
                const int lb = kc & 1;
                const unsigned* mrow = s_mask + (kc & 3) * CHUNK * 16;
                unsigned short* el = s_elist + lb * CAP_LIST;
                int running = 0;
                for (int e0 = 0; e0 < CHUNK; ++e0) {
                    unsigned m = (lane < 13) ? mrow[e0 * 16 + lane] : 0u;
                    int c = __popc(m);
                    // inclusive scan of c over lanes
                    int sc = c;
                    #pragma unroll
                    for (int d = 1; d < 32; d <<= 1) {
                        int v = __shfl_up_sync(0xffffffffu, sc, d);
                        if (lane >= d) sc += v;
                    }
                    int pos = running + (sc - c);
                    while (m) {
                        int bit = __ffs(m) - 1;
                        m &= m - 1;
                        if (pos < CAP_LIST)
                            el[pos] = (unsigned short)((lane << 5) + bit);
                        ++pos;
                    }
                    int tot_e = __shfl_sync(0xffffffffu, sc, 31);
                    if (lane == 0) {
                        s_off[lb * CHUNK + e0] = running;
                        s_cnt[lb * CHUNK + e0] = tot_e;
                    }
                    running += tot_e;
                }
                if (lane == 0) s_tot[lb] = running;
                __syncwarp();
                // gather weights for all spikes (fast path only)
                if (running <= CAP_WG) {
                    float* wg = s_wg + lb * CAP_WG * DOUT;
                    const int T = running * DOUT;
                    for (int x = lane; x < T; x += 32) {
                        int s = x / DOUT;
                        int d = x - s * DOUT;
                        int j = el[s];
                        wg[x] = s_W2c[j * DOUT + d];
                    }
                }
            }
        } else {
            // -------- chain: layer-2 membrane over chunk k-2 --------
            const int kc = k - 2;
            if (kc >= 0 && lane < DOUT) {
                const int lb = kc & 1;
                const int tot = s_tot[lb];
                if (tot <= CAP_WG) {
                    const float* wg = s_wg + lb * CAP_WG * DOUT + lane;
                    for (int e0 = 0; e0 < CHUNK; ++e0) {
                        const int e = kc * CHUNK + e0;
                        h2 = __fmul_rn(h2, s_dec2[e]);
                        const int base = s_off[lb * CHUNK + e0];
                        const int n    = s_cnt[lb * CHUNK + e0];
                        const float* wp = wg + base * DOUT;
                        #pragma unroll 4
                        for (int i = 0; i < n; ++i) {
                            h2 = __fadd_rn(h2, wp[i * DOUT]);
                            if (h2 >= 0.5f) { cnt += 1.0f; h2 = 0.0f; }
                        }
                    }
                } else if (tot <= CAP_LIST) {
                    const unsigned short* el = s_elist + lb * CAP_LIST;
                    for (int e0 = 0; e0 < CHUNK; ++e0) {
                        const int e = kc * CHUNK + e0;
                        h2 = __fmul_rn(h2, s_dec2[e]);
                        const int base = s_off[lb * CHUNK + e0];
                        const int n    = s_cnt[lb * CHUNK + e0];
                        for (int i = 0; i < n; ++i) {
                            int j = el[base + i];
                            h2 = __fadd_rn(h2, s_W2c[j * DOUT + lane]);
                            if (h2 >= 0.5f) { cnt += 1.0f; h2 = 0.0f; }
                        }
                    }
                } else {
                    const unsigned* mrow = s_mask + (kc & 3) * CHUNK * 16;
                    for (int e0 = 0; e0 < CHUNK; ++e0) {
                        const int e = kc * CHUNK + e0;
                        h2 = __fmul_rn(h2, s_dec2[e]);
                        for (int w = 0; w < 13; ++w) {
                            unsigned m = mrow[e0 * 16 + w];
                            while (m) {
                                int bit = __ffs(m) - 1;
                                m &= m - 1;
                                int j = (w << 5) + bit;
                                h2 = __fadd_rn(h2, s_W2c[j * DOUT + lane]);
                                if (h2 >= 0.5f) { cnt += 1.0f; h2 = 0.0f; }
                            }
                        }
                    }
                }
            }
        }
        __syncthreads();
    }

    if (warp == 13 && lane < DOUT)
        out[b * DOUT + lane] = __fdiv_rn(cnt, 64.0f);
}

extern "C" void kernel_launch(void* const* d_in, const int* in_sizes, int n_in,
                              void* d_out, int out_size) {
    const float* times = (const float*)d_in[0];  // [256,1024] f32
    const int*   pixv  = (const int*)d_in[1];    // [256,1024] i32
    const float* W1    = (const float*)d_in[2];  // [400,784]
    const float* b1    = (const float*)d_in[3];  // [400]
    const float* W2    = (const float*)d_in[4];  // [10,400]
    const float* b2    = (const float*)d_in[5];  // [10]

    static int smem_set = 0;
    if (!smem_set) {
        cudaFuncSetAttribute(snn_kernel,
                             cudaFuncAttributeMaxDynamicSharedMemorySize,
                             SM_BYTES);
        smem_set = 1;
    }

    prep_kernel<<<(DIN * DH + DH * DOUT + 255) / 256, 256>>>(W1, W2, b2);
    snn_kernel<<<B_SAMPLES, NTHREADS, SM_BYTES>>>(times, pixv, b1, (float*)d_out);
}